// round 1
// baseline (speedup 1.0000x reference)
#include <cuda_runtime.h>
#include <math.h>

// ---------------- problem constants ----------------
#define Bn    4
#define CIN   21
#define HIDC  96          // 48 (o-branch) + 48 (g-branch)
#define HL    81
#define WL    81
#define HW    6561        // 81*81
#define UP    4
#define HOUT  324
#define WOUT  324
#define HWO   104976      // 324*324

// output tuple layout: y [4,21,324,324] | v [4,8,81,81] | g_up [4,1,324,324]
#define OUT_V_OFF 8817984
#define OUT_G_OFF 9027936

// ---------------- scratch (static device globals; no allocation) ----------------
__device__ float g_hidden[Bn * HIDC * HW];   // relu(conv1) for both branches (~10.1 MB)
__device__ float g_raw[Bn * 9 * HW];         // v[0..7] (post-tanh) and g (post-sigmoid)
__device__ float g_ycomb[Bn * CIN * HW];     // lam*y_lp_out + tanh(beta)*g*y_hp  per lowres px
__device__ float g_lamb[Bn * HW];            // lam per lowres px

// ==========================================================================
// Kernel 1: conv1 for both branches fused (21 -> 96 channels), ReLU.
// grid: (12 spatial tiles, 12 co-groups of 8, 4 batch); block: 256 threads.
// Tile: 16 rows x 64 cols of output; thread computes a 1x4 strip x 8 co.
// Input channels staged through shared memory in chunks of 7.
// ==========================================================================
__global__ __launch_bounds__(256) void conv1_kernel(
    const float* __restrict__ x,
    const float* __restrict__ w1o, const float* __restrict__ b1o,
    const float* __restrict__ w1g, const float* __restrict__ b1g)
{
    __shared__ float sx[7 * 18 * 66];   // 7 ch x (16+2) rows x (64+2) cols
    __shared__ float sw[8 * 189];       // 8 co x 21 ci x 9 taps

    const int tile = blockIdx.x;          // 0..11
    const int cg   = blockIdx.y;          // 0..11 (8 output channels each)
    const int b    = blockIdx.z;
    const int ty   = tile >> 1, tx = tile & 1;
    const int row0 = ty * 16, col0 = tx * 64;
    const int tid  = threadIdx.x;

    // stage the 8 output-channel weight rows
    for (int i = tid; i < 8 * 189; i += 256) {
        int co = i / 189, j = i % 189;
        int co_out = cg * 8 + co;
        sw[i] = (co_out < 48) ? w1o[co_out * 189 + j] : w1g[(co_out - 48) * 189 + j];
    }

    const int tr  = tid >> 4;             // 0..15 row within tile
    const int tc4 = (tid & 15) << 2;      // 0..60 col strip start

    float acc[8][4];
#pragma unroll
    for (int a = 0; a < 8; ++a)
#pragma unroll
        for (int p = 0; p < 4; ++p) acc[a][p] = 0.f;

    for (int cc = 0; cc < 3; ++cc) {      // 3 chunks of 7 input channels
        __syncthreads();
        for (int i = tid; i < 7 * 18 * 66; i += 256) {
            int c   = i / 1188;
            int r   = (i / 66) % 18;
            int col = i % 66;
            int gy = row0 - 1 + r, gx = col0 - 1 + col;
            float v = 0.f;
            if (gy >= 0 && gy < HL && gx >= 0 && gx < WL)
                v = x[((b * CIN + cc * 7 + c) * HL + gy) * WL + gx];
            sx[i] = v;
        }
        __syncthreads();

#pragma unroll
        for (int c = 0; c < 7; ++c) {
#pragma unroll
            for (int ky = 0; ky < 3; ++ky) {
                const float* xr = &sx[(c * 18 + tr + ky) * 66 + tc4];
                float xv[6];
#pragma unroll
                for (int j = 0; j < 6; ++j) xv[j] = xr[j];
#pragma unroll
                for (int kx = 0; kx < 3; ++kx) {
                    const int wj = (cc * 7 + c) * 9 + ky * 3 + kx;
#pragma unroll
                    for (int co = 0; co < 8; ++co) {
                        const float wv = sw[co * 189 + wj];
                        acc[co][0] += xv[kx + 0] * wv;
                        acc[co][1] += xv[kx + 1] * wv;
                        acc[co][2] += xv[kx + 2] * wv;
                        acc[co][3] += xv[kx + 3] * wv;
                    }
                }
            }
        }
    }

    const int orow = row0 + tr;
    if (orow < HL) {
#pragma unroll
        for (int co = 0; co < 8; ++co) {
            const int co_out = cg * 8 + co;
            const float bias = (co_out < 48) ? b1o[co_out] : b1g[co_out - 48];
            float* dst = &g_hidden[(b * HIDC + co_out) * HW + orow * WL];
#pragma unroll
            for (int p = 0; p < 4; ++p) {
                const int ocol = col0 + tc4 + p;
                if (ocol < WL) dst[ocol] = fmaxf(acc[co][p] + bias, 0.f);
            }
        }
    }
}

// ==========================================================================
// Kernel 2: conv2 heads. co 0..7: tanh head over hidden[0..48) -> v (also to d_out).
//           co 8: sigmoid gate over hidden[48..96).
// grid: (12 tiles, 9 co, 4 b); block 256; thread = 1x4 strip, 1 co.
// ==========================================================================
__global__ __launch_bounds__(256) void conv2_kernel(
    const float* __restrict__ w2o, const float* __restrict__ b2o,
    const float* __restrict__ w2g, const float* __restrict__ b2g,
    float* __restrict__ out)
{
    __shared__ float sx[8 * 18 * 66];
    __shared__ float sw[48 * 9];

    const int tile = blockIdx.x;
    const int co   = blockIdx.y;          // 0..8
    const int b    = blockIdx.z;
    const int ty   = tile >> 1, tx = tile & 1;
    const int row0 = ty * 16, col0 = tx * 64;
    const int tid  = threadIdx.x;

    const int chbase = (co < 8) ? 0 : 48;
    const float* wsrc = (co < 8) ? (w2o + co * 48 * 9) : w2g;
    for (int i = tid; i < 48 * 9; i += 256) sw[i] = wsrc[i];

    const int tr  = tid >> 4;
    const int tc4 = (tid & 15) << 2;

    float acc[4] = {0.f, 0.f, 0.f, 0.f};

    for (int cc = 0; cc < 6; ++cc) {      // 6 chunks of 8 channels
        __syncthreads();
        for (int i = tid; i < 8 * 18 * 66; i += 256) {
            int c   = i / 1188;
            int r   = (i / 66) % 18;
            int col = i % 66;
            int gy = row0 - 1 + r, gx = col0 - 1 + col;
            float v = 0.f;
            if (gy >= 0 && gy < HL && gx >= 0 && gx < WL)
                v = g_hidden[(b * HIDC + chbase + cc * 8 + c) * HW + gy * WL + gx];
            sx[i] = v;
        }
        __syncthreads();

#pragma unroll
        for (int c = 0; c < 8; ++c) {
#pragma unroll
            for (int ky = 0; ky < 3; ++ky) {
                const float* xr = &sx[(c * 18 + tr + ky) * 66 + tc4];
                float xv[6];
#pragma unroll
                for (int j = 0; j < 6; ++j) xv[j] = xr[j];
#pragma unroll
                for (int kx = 0; kx < 3; ++kx) {
                    const float wv = sw[(cc * 8 + c) * 9 + ky * 3 + kx];
                    acc[0] += xv[kx + 0] * wv;
                    acc[1] += xv[kx + 1] * wv;
                    acc[2] += xv[kx + 2] * wv;
                    acc[3] += xv[kx + 3] * wv;
                }
            }
        }
    }

    const float bias = (co < 8) ? b2o[co] : b2g[0];
    const int orow = row0 + tr;
    if (orow < HL) {
#pragma unroll
        for (int p = 0; p < 4; ++p) {
            const int ocol = col0 + tc4 + p;
            if (ocol < WL) {
                const int pix = orow * WL + ocol;
                const float raw = acc[p] + bias;
                if (co < 8) {
                    const float v = tanhf(raw);             // VMAX = 1
                    g_raw[(b * 9 + co) * HW + pix] = v;
                    out[OUT_V_OFF + (b * 8 + co) * HW + pix] = v;
                } else {
                    g_raw[(b * 9 + 8) * HW + pix] = 1.f / (1.f + expf(-raw));
                }
            }
        }
    }
}

// ==========================================================================
// Kernel 3: per-lowres-pixel fusion.
// Closed-form GL kernel (M=1): with p_i = v_i - v_{i+4},
//   k00=(p0+p1+p2)/8 k01=(p1+p2+p3)/8 k02=(-p0+p2+p3)/8 k10=(p0+p1-p3)/8
//   center 0 (+2.5 bias), bottom half antisymmetric.
// Builds combined mask wm = lam*softmax(ker/tau) + tanh(beta)*g*hp,
// gathers reflect-padded 3x3 patches for 21 channels -> g_ycomb, g_lamb.
// ==========================================================================
__global__ void fuse_kernel(const float* __restrict__ x, const float* __restrict__ beta)
{
    const int idx = blockIdx.x * blockDim.x + threadIdx.x;
    if (idx >= Bn * HW) return;
    const int b = idx / HW, pix = idx % HW;
    const int y = pix / WL, xx = pix % WL;

    const float* vr = g_raw + b * 9 * HW;
    const float v0 = vr[0 * HW + pix], v1 = vr[1 * HW + pix];
    const float v2 = vr[2 * HW + pix], v3 = vr[3 * HW + pix];
    const float v4 = vr[4 * HW + pix], v5 = vr[5 * HW + pix];
    const float v6 = vr[6 * HW + pix], v7 = vr[7 * HW + pix];
    const float g  = vr[8 * HW + pix];

    const float p0 = v0 - v4, p1 = v1 - v5, p2 = v2 - v6, p3 = v3 - v7;
    const float k00 = (p0 + p1 + p2) * 0.125f;
    const float k01 = (p1 + p2 + p3) * 0.125f;
    const float k02 = (-p0 + p2 + p3) * 0.125f;
    const float k10 = (p0 + p1 - p3) * 0.125f;

    float kb[9];
    kb[0] = k00;  kb[1] = k01;  kb[2] = k02;
    kb[3] = k10;  kb[4] = 2.5f; kb[5] = -k10;
    kb[6] = -k02; kb[7] = -k01; kb[8] = -k00;

    float mx = kb[0];
#pragma unroll
    for (int n = 1; n < 9; ++n) mx = fmaxf(mx, kb[n]);
    float e[9], se = 0.f;
#pragma unroll
    for (int n = 0; n < 9; ++n) { e[n] = expf((kb[n] - mx) * 2.0f); se += e[n]; }  // /tau = *2
    const float inv_se = 1.0f / se;

    const float mean = 2.5f / 9.0f;   // off-center entries sum to 0
    float hp[9], sa = 0.f;
#pragma unroll
    for (int n = 0; n < 9; ++n) { hp[n] = kb[n] - mean; sa += fabsf(hp[n]); }
    const float hinv = 1.0f / (sa + 1e-8f);

    const float lam = 0.15f * (1.0f - g);
    const float tbg = tanhf(beta[0]) * g;

    float wm[9];
#pragma unroll
    for (int n = 0; n < 9; ++n) wm[n] = lam * e[n] * inv_se + tbg * hp[n] * hinv;

    // reflect padding indices
    const int ym = (y == 0) ? 1 : y - 1,   yp = (y == HL - 1) ? HL - 2 : y + 1;
    const int xm = (xx == 0) ? 1 : xx - 1, xp = (xx == WL - 1) ? WL - 2 : xx + 1;
    const int ry[3] = {ym, y, yp};
    const int rx[3] = {xm, xx, xp};

    for (int ci = 0; ci < CIN; ++ci) {
        const float* xb = x + (b * CIN + ci) * HW;
        float a = 0.f;
#pragma unroll
        for (int i = 0; i < 3; ++i)
#pragma unroll
            for (int j = 0; j < 3; ++j)
                a += xb[ry[i] * WL + rx[j]] * wm[i * 3 + j];
        g_ycomb[(b * CIN + ci) * HW + pix] = a;
    }
    g_lamb[b * HW + pix] = lam;
}

// ==========================================================================
// Kernel 4: high-res outputs. c<21 -> y = x_up*(1-lam) + ycomb ; c==21 -> g_up.
// ==========================================================================
__global__ void final_kernel(const float* __restrict__ x, float* __restrict__ out)
{
    const int idx = blockIdx.x * blockDim.x + threadIdx.x;
    if (idx >= Bn * 22 * HWO) return;
    const int b  = idx / (22 * HWO);
    const int r  = idx % (22 * HWO);
    const int c  = r / HWO;
    const int op = r % HWO;
    const int Y = op / WOUT, X = op % WOUT;
    const int yl = Y >> 2, xl = X >> 2;
    const int lpix = yl * WL + xl;

    if (c == 21) {
        out[OUT_G_OFF + b * HWO + op] = g_raw[(b * 9 + 8) * HW + lpix];
        return;
    }

    // bilinear, align_corners=True: src = i * (h-1)/(H-1)
    float fy = (float)(Y * (HL - 1)) * (1.0f / (float)(HOUT - 1));
    int iy = (int)fy; if (iy > HL - 2) iy = HL - 2;
    const float wy = fy - (float)iy;
    float fx = (float)(X * (WL - 1)) * (1.0f / (float)(WOUT - 1));
    int ix = (int)fx; if (ix > WL - 2) ix = WL - 2;
    const float wx = fx - (float)ix;

    const float* xb = x + (b * CIN + c) * HW;
    const int o = iy * WL + ix;
    const float x00 = xb[o], x01 = xb[o + 1], x10 = xb[o + WL], x11 = xb[o + WL + 1];
    const float xu = x00 * (1.f - wy) * (1.f - wx) + x01 * (1.f - wy) * wx
                   + x10 * wy * (1.f - wx) + x11 * wy * wx;

    const float lam = g_lamb[b * HW + lpix];
    out[(b * CIN + c) * HWO + op] = xu * (1.0f - lam) + g_ycomb[(b * CIN + c) * HW + lpix];
}

// ==========================================================================
extern "C" void kernel_launch(void* const* d_in, const int* in_sizes, int n_in,
                              void* d_out, int out_size)
{
    const float* x    = (const float*)d_in[0];
    const float* w1o  = (const float*)d_in[1];
    const float* b1o  = (const float*)d_in[2];
    const float* w2o  = (const float*)d_in[3];
    const float* b2o  = (const float*)d_in[4];
    const float* w1g  = (const float*)d_in[5];
    const float* b1g  = (const float*)d_in[6];
    const float* w2g  = (const float*)d_in[7];
    const float* b2g  = (const float*)d_in[8];
    const float* beta = (const float*)d_in[9];
    float* out = (float*)d_out;

    conv1_kernel<<<dim3(12, 12, Bn), 256>>>(x, w1o, b1o, w1g, b1g);
    conv2_kernel<<<dim3(12, 9, Bn), 256>>>(w2o, b2o, w2g, b2g, out);
    fuse_kernel<<<(Bn * HW + 255) / 256, 256>>>(x, beta);
    final_kernel<<<(Bn * 22 * HWO + 255) / 256, 256>>>(x, out);
}

// round 2
// speedup vs baseline: 1.3364x; 1.3364x over previous
#include <cuda_runtime.h>
#include <math.h>

// ---------------- problem constants ----------------
#define Bn    4
#define CIN   21
#define HIDC  96
#define HL    81
#define WL    81
#define HW    6561
#define HOUT  324
#define WOUT  324
#define HWO   104976

#define OUT_V_OFF 8817984
#define OUT_G_OFF 9027936

// ---------------- scratch ----------------
__device__ float g_hidden[Bn * HIDC * HW];
__device__ float g_raw[Bn * 9 * HW];       // v0..7 (tanh), g (sigmoid)
__device__ float g_ycomb[Bn * CIN * HW];
__device__ float g_lamb[Bn * HW];

// ---------------- packed fp32x2 helpers ----------------
__device__ __forceinline__ unsigned long long pkf2(float lo, float hi) {
    unsigned long long r;
    asm("mov.b64 %0, {%1,%2};" : "=l"(r) : "f"(lo), "f"(hi));
    return r;
}
__device__ __forceinline__ void upkf2(unsigned long long v, float& lo, float& hi) {
    asm("mov.b64 {%0,%1}, %2;" : "=f"(lo), "=f"(hi) : "l"(v));
}
__device__ __forceinline__ void ffma2(unsigned long long& d, unsigned long long a, unsigned long long b) {
    asm("fma.rn.f32x2 %0, %1, %2, %0;" : "+l"(d) : "l"(a), "l"(b));
}

// ==========================================================================
// Kernel 1: conv1 both branches (21 -> 96), ReLU. Packed f32x2 FMA.
// grid (7 row-tiles, 12 co-groups, 4 b); block 256 (252 active).
// Tile: 12 rows x 81 cols (staged 14 x 86, stride 88). Thread: 1x4 strip x 8 co.
// ==========================================================================
__global__ __launch_bounds__(256) void conv1_kernel(
    const float* __restrict__ x,
    const float* __restrict__ w1o, const float* __restrict__ b1o,
    const float* __restrict__ w1g, const float* __restrict__ b1g)
{
    __shared__ __align__(16) float sx[7 * 14 * 88];          // 34.5 KB
    __shared__ unsigned long long sw2[8 * 189];               // 12.1 KB (dup pairs)

    const int tile = blockIdx.x;
    const int cg   = blockIdx.y;
    const int b    = blockIdx.z;
    const int row0 = tile * 12;
    const int tid  = threadIdx.x;

    for (int i = tid; i < 8 * 189; i += 256) {
        int co = i / 189, j = i % 189;
        int co_out = cg * 8 + co;
        float w = (co_out < 48) ? w1o[co_out * 189 + j] : w1g[(co_out - 48) * 189 + j];
        sw2[i] = pkf2(w, w);
    }

    const bool active = tid < 252;
    const int tr  = active ? (tid / 21) : 0;       // 0..11
    const int tc4 = active ? ((tid % 21) << 2) : 0; // 0,4,...,80

    unsigned long long acc[8][2];
#pragma unroll
    for (int co = 0; co < 8; ++co) { acc[co][0] = 0ULL; acc[co][1] = 0ULL; }

    for (int cc = 0; cc < 3; ++cc) {
        __syncthreads();
        for (int i = tid; i < 7 * 14 * 86; i += 256) {
            int c   = i / 1204;          // 14*86
            int r   = (i / 86) % 14;
            int col = i % 86;
            int gy = row0 - 1 + r, gx = col - 1;
            float v = 0.f;
            if (gy >= 0 && gy < HL && gx >= 0 && gx < WL)
                v = x[((b * CIN + cc * 7 + c) * HL + gy) * WL + gx];
            sx[(c * 14 + r) * 88 + col] = v;
        }
        __syncthreads();

#pragma unroll
        for (int c = 0; c < 7; ++c) {
#pragma unroll
            for (int ky = 0; ky < 3; ++ky) {
                const float2* rowp = (const float2*)&sx[(c * 14 + tr + ky) * 88 + tc4];
                const float2 A = rowp[0], B = rowp[1], C = rowp[2];
                unsigned long long pa[3], pb[3];
                pa[0] = pkf2(A.x, A.y); pa[1] = pkf2(A.y, B.x); pa[2] = pkf2(B.x, B.y);
                pb[0] = pa[2];          pb[1] = pkf2(B.y, C.x); pb[2] = pkf2(C.x, C.y);
                const int wj = (cc * 7 + c) * 9 + ky * 3;
#pragma unroll
                for (int kx = 0; kx < 3; ++kx) {
#pragma unroll
                    for (int co = 0; co < 8; ++co) {
                        const unsigned long long w2 = sw2[co * 189 + wj + kx];
                        ffma2(acc[co][0], pa[kx], w2);
                        ffma2(acc[co][1], pb[kx], w2);
                    }
                }
            }
        }
    }

    const int orow = row0 + tr;
    if (active && orow < HL) {
#pragma unroll
        for (int co = 0; co < 8; ++co) {
            const int co_out = cg * 8 + co;
            const float bias = (co_out < 48) ? b1o[co_out] : b1g[co_out - 48];
            float r0, r1, r2, r3;
            upkf2(acc[co][0], r0, r1);
            upkf2(acc[co][1], r2, r3);
            float vv[4] = {r0, r1, r2, r3};
            float* dst = &g_hidden[(b * HIDC + co_out) * HW + orow * WL];
#pragma unroll
            for (int p = 0; p < 4; ++p) {
                const int ocol = tc4 + p;
                if (ocol < WL) dst[ocol] = fmaxf(vv[p] + bias, 0.f);
            }
        }
    }
}

// ==========================================================================
// Kernel 2: conv2 heads (48->1 per block-co), tanh/sigmoid. Packed f32x2.
// grid (7 row-tiles, 9 co, 4 b); block 256 (252 active).
// ==========================================================================
__global__ __launch_bounds__(256) void conv2_kernel(
    const float* __restrict__ w2o, const float* __restrict__ b2o,
    const float* __restrict__ w2g, const float* __restrict__ b2g,
    float* __restrict__ out)
{
    __shared__ __align__(16) float sx[6 * 14 * 88];           // 29.6 KB
    __shared__ unsigned long long sw2[48 * 9];                 // 3.5 KB

    const int tile = blockIdx.x;
    const int co   = blockIdx.y;          // 0..8
    const int b    = blockIdx.z;
    const int row0 = tile * 12;
    const int tid  = threadIdx.x;

    const int chbase = (co < 8) ? 0 : 48;
    const float* wsrc = (co < 8) ? (w2o + co * 432) : w2g;
    for (int i = tid; i < 432; i += 256) sw2[i] = pkf2(wsrc[i], wsrc[i]);

    const bool active = tid < 252;
    const int tr  = active ? (tid / 21) : 0;
    const int tc4 = active ? ((tid % 21) << 2) : 0;

    unsigned long long a0 = 0ULL, a1 = 0ULL;

    for (int cc = 0; cc < 8; ++cc) {      // 8 chunks of 6 channels
        __syncthreads();
        for (int i = tid; i < 6 * 14 * 86; i += 256) {
            int c   = i / 1204;
            int r   = (i / 86) % 14;
            int col = i % 86;
            int gy = row0 - 1 + r, gx = col - 1;
            float v = 0.f;
            if (gy >= 0 && gy < HL && gx >= 0 && gx < WL)
                v = g_hidden[(b * HIDC + chbase + cc * 6 + c) * HW + gy * WL + gx];
            sx[(c * 14 + r) * 88 + col] = v;
        }
        __syncthreads();

#pragma unroll
        for (int c = 0; c < 6; ++c) {
#pragma unroll
            for (int ky = 0; ky < 3; ++ky) {
                const float2* rowp = (const float2*)&sx[(c * 14 + tr + ky) * 88 + tc4];
                const float2 A = rowp[0], B = rowp[1], C = rowp[2];
                unsigned long long pa[3], pb[3];
                pa[0] = pkf2(A.x, A.y); pa[1] = pkf2(A.y, B.x); pa[2] = pkf2(B.x, B.y);
                pb[0] = pa[2];          pb[1] = pkf2(B.y, C.x); pb[2] = pkf2(C.x, C.y);
                const int wj = (cc * 6 + c) * 9 + ky * 3;
#pragma unroll
                for (int kx = 0; kx < 3; ++kx) {
                    const unsigned long long w2 = sw2[wj + kx];
                    ffma2(a0, pa[kx], w2);
                    ffma2(a1, pb[kx], w2);
                }
            }
        }
    }

    const float bias = (co < 8) ? b2o[co] : b2g[0];
    const int orow = row0 + tr;
    if (active && orow < HL) {
        float r0, r1, r2, r3;
        upkf2(a0, r0, r1);
        upkf2(a1, r2, r3);
        float vv[4] = {r0, r1, r2, r3};
#pragma unroll
        for (int p = 0; p < 4; ++p) {
            const int ocol = tc4 + p;
            if (ocol < WL) {
                const int pix = orow * WL + ocol;
                const float raw = vv[p] + bias;
                if (co < 8) {
                    const float v = tanhf(raw);
                    g_raw[(b * 9 + co) * HW + pix] = v;
                    out[OUT_V_OFF + (b * 8 + co) * HW + pix] = v;
                } else {
                    g_raw[(b * 9 + 8) * HW + pix] = 1.f / (1.f + expf(-raw));
                }
            }
        }
    }
}

// ==========================================================================
// Kernel 3: per-lowres-pixel fusion (7-channel groups for parallelism).
// grid (26, 3, 4); block 256.
// ==========================================================================
__global__ void fuse_kernel(const float* __restrict__ x, const float* __restrict__ beta)
{
    const int pix = blockIdx.x * blockDim.x + threadIdx.x;
    if (pix >= HW) return;
    const int grp = blockIdx.y;     // 0..2  (channels grp*7 .. grp*7+6)
    const int b   = blockIdx.z;
    const int y = pix / WL, xx = pix % WL;

    const float* vr = g_raw + b * 9 * HW;
    const float v0 = vr[0 * HW + pix], v1 = vr[1 * HW + pix];
    const float v2 = vr[2 * HW + pix], v3 = vr[3 * HW + pix];
    const float v4 = vr[4 * HW + pix], v5 = vr[5 * HW + pix];
    const float v6 = vr[6 * HW + pix], v7 = vr[7 * HW + pix];
    const float g  = vr[8 * HW + pix];

    const float p0 = v0 - v4, p1 = v1 - v5, p2 = v2 - v6, p3 = v3 - v7;
    const float k00 = (p0 + p1 + p2) * 0.125f;
    const float k01 = (p1 + p2 + p3) * 0.125f;
    const float k02 = (-p0 + p2 + p3) * 0.125f;
    const float k10 = (p0 + p1 - p3) * 0.125f;

    float kb[9];
    kb[0] = k00;  kb[1] = k01;  kb[2] = k02;
    kb[3] = k10;  kb[4] = 2.5f; kb[5] = -k10;
    kb[6] = -k02; kb[7] = -k01; kb[8] = -k00;

    float mx = kb[0];
#pragma unroll
    for (int n = 1; n < 9; ++n) mx = fmaxf(mx, kb[n]);
    float e[9], se = 0.f;
#pragma unroll
    for (int n = 0; n < 9; ++n) { e[n] = expf((kb[n] - mx) * 2.0f); se += e[n]; }
    const float inv_se = 1.0f / se;

    const float mean = 2.5f / 9.0f;
    float hp[9], sa = 0.f;
#pragma unroll
    for (int n = 0; n < 9; ++n) { hp[n] = kb[n] - mean; sa += fabsf(hp[n]); }
    const float hinv = 1.0f / (sa + 1e-8f);

    const float lam = 0.15f * (1.0f - g);
    const float tbg = tanhf(beta[0]) * g;

    float wm[9];
#pragma unroll
    for (int n = 0; n < 9; ++n) wm[n] = lam * e[n] * inv_se + tbg * hp[n] * hinv;

    const int ym = (y == 0) ? 1 : y - 1,   yp = (y == HL - 1) ? HL - 2 : y + 1;
    const int xm = (xx == 0) ? 1 : xx - 1, xp = (xx == WL - 1) ? WL - 2 : xx + 1;
    const int ry[3] = {ym, y, yp};
    const int rx[3] = {xm, xx, xp};

#pragma unroll
    for (int cl = 0; cl < 7; ++cl) {
        const int ci = grp * 7 + cl;
        const float* xb = x + (b * CIN + ci) * HW;
        float a = 0.f;
#pragma unroll
        for (int i = 0; i < 3; ++i)
#pragma unroll
            for (int j = 0; j < 3; ++j)
                a += xb[ry[i] * WL + rx[j]] * wm[i * 3 + j];
        g_ycomb[(b * CIN + ci) * HW + pix] = a;
    }
    if (grp == 0) g_lamb[b * HW + pix] = lam;
}

// ==========================================================================
// Kernel 4: high-res. Thread = one 4px quad, float4 store, no div/mod.
// block (81,3); grid (108, 22, 4). c==21 -> g_up channel.
// ==========================================================================
__global__ __launch_bounds__(256) void final_kernel(
    const float* __restrict__ x, float* __restrict__ out)
{
    const int qx = threadIdx.x;                    // 0..80
    const int Y  = blockIdx.x * 3 + threadIdx.y;   // 0..323
    const int c  = blockIdx.y;                     // 0..21
    const int b  = blockIdx.z;
    const int lpix = (Y >> 2) * WL + qx;

    if (c == 21) {
        const float gv = g_raw[(b * 9 + 8) * HW + lpix];
        float4 o = make_float4(gv, gv, gv, gv);
        *(float4*)&out[OUT_G_OFF + b * HWO + Y * WOUT + qx * 4] = o;
        return;
    }

    const float sc = 80.0f / 323.0f;
    const float fy = (float)Y * sc;
    int iy = (int)fy; if (iy > HL - 2) iy = HL - 2;
    const float wy = fy - (float)iy;

    const float lam = g_lamb[b * HW + lpix];
    const float yc  = g_ycomb[(b * CIN + c) * HW + lpix];
    const float oml = 1.0f - lam;

    const float* xb = x + (b * CIN + c) * HW + iy * WL;
    float res[4];
#pragma unroll
    for (int j = 0; j < 4; ++j) {
        const int X = qx * 4 + j;
        const float fx = (float)X * sc;
        int ix = (int)fx; if (ix > WL - 2) ix = WL - 2;
        const float wx = fx - (float)ix;
        const float x00 = xb[ix], x01 = xb[ix + 1];
        const float x10 = xb[ix + WL], x11 = xb[ix + WL + 1];
        const float top = x00 + (x01 - x00) * wx;
        const float bot = x10 + (x11 - x10) * wx;
        const float xu  = top + (bot - top) * wy;
        res[j] = xu * oml + yc;
    }
    float4 o = make_float4(res[0], res[1], res[2], res[3]);
    *(float4*)&out[(b * CIN + c) * HWO + Y * WOUT + qx * 4] = o;
}

// ==========================================================================
extern "C" void kernel_launch(void* const* d_in, const int* in_sizes, int n_in,
                              void* d_out, int out_size)
{
    const float* x    = (const float*)d_in[0];
    const float* w1o  = (const float*)d_in[1];
    const float* b1o  = (const float*)d_in[2];
    const float* w2o  = (const float*)d_in[3];
    const float* b2o  = (const float*)d_in[4];
    const float* w1g  = (const float*)d_in[5];
    const float* b1g  = (const float*)d_in[6];
    const float* w2g  = (const float*)d_in[7];
    const float* b2g  = (const float*)d_in[8];
    const float* beta = (const float*)d_in[9];
    float* out = (float*)d_out;

    conv1_kernel<<<dim3(7, 12, Bn), 256>>>(x, w1o, b1o, w1g, b1g);
    conv2_kernel<<<dim3(7, 9, Bn), 256>>>(w2o, b2o, w2g, b2g, out);
    fuse_kernel<<<dim3(26, 3, Bn), 256>>>(x, beta);
    final_kernel<<<dim3(108, 22, Bn), dim3(81, 3, 1)>>>(x, out);
}

// round 4
// speedup vs baseline: 1.9033x; 1.4242x over previous
#include <cuda_runtime.h>
#include <math.h>

typedef unsigned long long ull;

// ---------------- problem constants ----------------
#define Bn    4
#define CIN   21
#define HL    81
#define WL    81
#define HW    6561
#define HWO   104976
#define WOUTX 324
#define XPH   83
#define XPW   88
#define XPP   7304        // 83*88

#define OUT_V_OFF 8817984
#define OUT_G_OFF 9027936

// ---------------- scratch ----------------
__device__ float g_xpad[Bn * CIN * XPP];
__device__ float g_hidden[Bn * 96 * XPP];
__device__ float g_raw[Bn * 9 * HW];
__device__ float g_ycomb[Bn * CIN * HW];
__device__ float g_lamb[Bn * HW];

// ---------------- packed fp32x2 helpers ----------------
__device__ __forceinline__ ull pkf2(float lo, float hi) {
    ull r; asm("mov.b64 %0, {%1,%2};" : "=l"(r) : "f"(lo), "f"(hi)); return r;
}
__device__ __forceinline__ void upkf2(ull v, float& lo, float& hi) {
    asm("mov.b64 {%0,%1}, %2;" : "=f"(lo), "=f"(hi) : "l"(v));
}
__device__ __forceinline__ void ffma2(ull& d, ull a, ull b) {
    asm("fma.rn.f32x2 %0, %1, %2, %0;" : "+l"(d) : "l"(a), "l"(b));
}
__device__ __forceinline__ ull hilo(ull a, ull b) {
    float al, ah, bl, bh; upkf2(a, al, ah); upkf2(b, bl, bh); return pkf2(ah, bl);
}

// ==========================================================================
// Kernel 0: build xpad (zero halo) + zero hidden halos/tails.
// ==========================================================================
#define PAD_N1 (Bn * CIN * XPP)
#define PAD_N2 (Bn * 96 * 744)
__global__ void pad_kernel(const float* __restrict__ x)
{
    const int idx = blockIdx.x * 256 + threadIdx.x;
    if (idx < PAD_N1) {
        const int plane = idx / XPP;
        const int rem   = idx - plane * XPP;
        const int r     = rem / XPW;
        const int col   = rem - r * XPW;
        float v = 0.f;
        if (r >= 1 && r <= HL && col >= 1 && col <= WL)
            v = x[plane * HW + (r - 1) * WL + (col - 1)];
        g_xpad[idx] = v;
    } else if (idx < PAD_N1 + PAD_N2) {
        const int j2    = idx - PAD_N1;
        const int plane = j2 / 744;
        const int j     = j2 - plane * 744;
        int off;
        if (j < 88)       off = j;                      // top halo row
        else if (j < 176) off = 82 * XPW + (j - 88);    // bottom halo row
        else {
            const int jj = j - 176;
            const int rr = 1 + jj / 7;
            const int cc = jj - (jj / 7) * 7;
            off = rr * XPW + ((cc == 0) ? 0 : 81 + cc); // col 0 + cols 82..87
        }
        g_hidden[plane * XPP + off] = 0.f;
    }
}

// ==========================================================================
// Kernel 1: conv1 (21 -> 96), ReLU. 3 rows x 4 px x 4 co per thread.
// ==========================================================================
__global__ __launch_bounds__(192) void conv1_kernel(
    const float* __restrict__ w1o, const float* __restrict__ b1o,
    const float* __restrict__ w1g, const float* __restrict__ b1g)
{
    __shared__ __align__(16) float sx[3 * 29 * XPW];
    __shared__ ull sw2[4 * 189];

    const int tile = blockIdx.x;
    const int cg   = blockIdx.y;
    const int b    = blockIdx.z;
    const int r0   = tile * 27;
    const int tid  = threadIdx.x;

    for (int i = tid; i < 4 * 189; i += 192) {
        const int co = i / 189, j = i - co * 189;
        const int co_out = cg * 4 + co;
        const float w = (co_out < 48) ? w1o[co_out * 189 + j] : w1g[(co_out - 48) * 189 + j];
        sw2[i] = pkf2(w, w);
    }

    const bool active = tid < 189;
    const int trp = active ? (tid / 21) : 0;
    const int tc  = active ? ((tid - trp * 21) * 4) : 0;
    const int trp3 = trp * 3;
    const int nvalid = (tc == 80) ? 1 : 4;     // last strip: only col 80 valid

    ull acc[4][3][2];
#pragma unroll
    for (int co = 0; co < 4; ++co)
#pragma unroll
        for (int r = 0; r < 3; ++r) { acc[co][r][0] = 0ULL; acc[co][r][1] = 0ULL; }

    for (int cc = 0; cc < 7; ++cc) {
        __syncthreads();
        for (int i = tid; i < 3 * 29 * 22; i += 192) {
            const int c  = i / 638;
            const int rm = i - c * 638;
            const int lr = rm / 22;
            const int f4 = rm - lr * 22;
            ((float4*)sx)[(c * 29 + lr) * 22 + f4] =
                ((const float4*)g_xpad)[((b * CIN + cc * 3 + c) * XPP + (r0 + lr) * XPW) / 4 + f4];
        }
        __syncthreads();

        if (active) {
#pragma unroll
            for (int c = 0; c < 3; ++c) {
                ull PA[5], PAB[5], PB[5], PBC[5], PC[5];
#pragma unroll
                for (int rr = 0; rr < 5; ++rr) {
                    const float* rp = &sx[(c * 29 + trp3 + rr) * XPW + tc];
                    const ull A  = *(const ull*)rp;
                    const ull Bv = *(const ull*)(rp + 2);
                    const ull Cv = *(const ull*)(rp + 4);
                    PA[rr] = A; PB[rr] = Bv; PC[rr] = Cv;
                    PAB[rr] = hilo(A, Bv); PBC[rr] = hilo(Bv, Cv);
                }
                const int wb = (cc * 3 + c) * 9;
#pragma unroll
                for (int ky = 0; ky < 3; ++ky)
#pragma unroll
                    for (int kx = 0; kx < 3; ++kx)
#pragma unroll
                        for (int co = 0; co < 4; ++co) {
                            const ull w = sw2[co * 189 + wb + ky * 3 + kx];
#pragma unroll
                            for (int r = 0; r < 3; ++r) {
                                const int rw = r + ky;
                                ffma2(acc[co][r][0],
                                      kx == 0 ? PA[rw] : (kx == 1 ? PAB[rw] : PB[rw]), w);
                                ffma2(acc[co][r][1],
                                      kx == 0 ? PB[rw] : (kx == 1 ? PBC[rw] : PC[rw]), w);
                            }
                        }
            }
        }
    }

    if (active) {
#pragma unroll
        for (int co = 0; co < 4; ++co) {
            const int co_out = cg * 4 + co;
            const float bias = (co_out < 48) ? b1o[co_out] : b1g[co_out - 48];
#pragma unroll
            for (int r = 0; r < 3; ++r) {
                const int orow = r0 + trp3 + r;
                float* dst = &g_hidden[(b * 96 + co_out) * XPP + (orow + 1) * XPW + tc + 1];
                float v[4];
                upkf2(acc[co][r][0], v[0], v[1]);
                upkf2(acc[co][r][1], v[2], v[3]);
#pragma unroll
                for (int p = 0; p < 4; ++p)
                    if (p < nvalid) dst[p] = fmaxf(v[p] + bias, 0.f);
            }
        }
    }
}

// ==========================================================================
// Kernel 2: conv2 heads. 3 rows x 4 px x 1 co per thread.
// ==========================================================================
__global__ __launch_bounds__(64) void conv2_kernel(
    const float* __restrict__ w2o, const float* __restrict__ b2o,
    const float* __restrict__ w2g, const float* __restrict__ b2g,
    float* __restrict__ out)
{
    __shared__ __align__(16) float sx[3 * 11 * XPW];
    __shared__ ull sw2[432];

    const int tile = blockIdx.x;
    const int co   = blockIdx.y;
    const int b    = blockIdx.z;
    const int r0   = tile * 9;
    const int tid  = threadIdx.x;

    const int chbase = (co < 8) ? 0 : 48;
    const float* wsrc = (co < 8) ? (w2o + co * 432) : w2g;
    for (int i = tid; i < 432; i += 64) sw2[i] = pkf2(wsrc[i], wsrc[i]);

    const bool active = tid < 63;
    const int trp = active ? (tid / 21) : 0;
    const int tc  = active ? ((tid - trp * 21) * 4) : 0;
    const int trp3 = trp * 3;
    const int nvalid = (tc == 80) ? 1 : 4;

    ull acc[3][2];
#pragma unroll
    for (int r = 0; r < 3; ++r) { acc[r][0] = 0ULL; acc[r][1] = 0ULL; }

    for (int cc = 0; cc < 16; ++cc) {
        __syncthreads();
        for (int i = tid; i < 3 * 11 * 22; i += 64) {
            const int c  = i / 242;
            const int rm = i - c * 242;
            const int lr = rm / 22;
            const int f4 = rm - lr * 22;
            ((float4*)sx)[(c * 11 + lr) * 22 + f4] =
                ((const float4*)g_hidden)[((b * 96 + chbase + cc * 3 + c) * XPP + (r0 + lr) * XPW) / 4 + f4];
        }
        __syncthreads();

        if (active) {
#pragma unroll
            for (int c = 0; c < 3; ++c) {
                ull PA[5], PAB[5], PB[5], PBC[5], PC[5];
#pragma unroll
                for (int rr = 0; rr < 5; ++rr) {
                    const float* rp = &sx[(c * 11 + trp3 + rr) * XPW + tc];
                    const ull A  = *(const ull*)rp;
                    const ull Bv = *(const ull*)(rp + 2);
                    const ull Cv = *(const ull*)(rp + 4);
                    PA[rr] = A; PB[rr] = Bv; PC[rr] = Cv;
                    PAB[rr] = hilo(A, Bv); PBC[rr] = hilo(Bv, Cv);
                }
                const int wb = (cc * 3 + c) * 9;
#pragma unroll
                for (int ky = 0; ky < 3; ++ky)
#pragma unroll
                    for (int kx = 0; kx < 3; ++kx) {
                        const ull w = sw2[wb + ky * 3 + kx];
#pragma unroll
                        for (int r = 0; r < 3; ++r) {
                            const int rw = r + ky;
                            ffma2(acc[r][0],
                                  kx == 0 ? PA[rw] : (kx == 1 ? PAB[rw] : PB[rw]), w);
                            ffma2(acc[r][1],
                                  kx == 0 ? PB[rw] : (kx == 1 ? PBC[rw] : PC[rw]), w);
                        }
                    }
            }
        }
    }

    if (active) {
        const float bias = (co < 8) ? b2o[co] : b2g[0];
#pragma unroll
        for (int r = 0; r < 3; ++r) {
            const int orow = r0 + trp3 + r;
            float v[4];
            upkf2(acc[r][0], v[0], v[1]);
            upkf2(acc[r][1], v[2], v[3]);
#pragma unroll
            for (int p = 0; p < 4; ++p) {
                if (p >= nvalid) continue;
                const int pix = orow * WL + tc + p;
                const float raw = v[p] + bias;
                if (co < 8) {
                    const float t = tanhf(raw);
                    g_raw[(b * 9 + co) * HW + pix] = t;
                    out[OUT_V_OFF + (b * 8 + co) * HW + pix] = t;
                } else {
                    g_raw[(b * 9 + 8) * HW + pix] = 1.f / (1.f + expf(-raw));
                }
            }
        }
    }
}

// ==========================================================================
// Kernel 3: per-lowres-pixel fusion.
// ==========================================================================
__global__ void fuse_kernel(const float* __restrict__ x, const float* __restrict__ beta)
{
    const int pix = blockIdx.x * blockDim.x + threadIdx.x;
    if (pix >= HW) return;
    const int grp = blockIdx.y;
    const int b   = blockIdx.z;
    const int y = pix / WL, xx = pix - y * WL;

    const float* vr = g_raw + b * 9 * HW;
    const float p0 = vr[0 * HW + pix] - vr[4 * HW + pix];
    const float p1 = vr[1 * HW + pix] - vr[5 * HW + pix];
    const float p2 = vr[2 * HW + pix] - vr[6 * HW + pix];
    const float p3 = vr[3 * HW + pix] - vr[7 * HW + pix];
    const float g  = vr[8 * HW + pix];

    const float k00 = (p0 + p1 + p2) * 0.125f;
    const float k01 = (p1 + p2 + p3) * 0.125f;
    const float k02 = (-p0 + p2 + p3) * 0.125f;
    const float k10 = (p0 + p1 - p3) * 0.125f;

    float kb[9];
    kb[0] = k00;  kb[1] = k01;  kb[2] = k02;
    kb[3] = k10;  kb[4] = 2.5f; kb[5] = -k10;
    kb[6] = -k02; kb[7] = -k01; kb[8] = -k00;

    float mx = kb[0];
#pragma unroll
    for (int n = 1; n < 9; ++n) mx = fmaxf(mx, kb[n]);
    float e[9], se = 0.f;
#pragma unroll
    for (int n = 0; n < 9; ++n) { e[n] = expf((kb[n] - mx) * 2.0f); se += e[n]; }
    const float inv_se = 1.0f / se;

    const float mean = 2.5f / 9.0f;
    float hp[9], sa = 0.f;
#pragma unroll
    for (int n = 0; n < 9; ++n) { hp[n] = kb[n] - mean; sa += fabsf(hp[n]); }
    const float hinv = 1.0f / (sa + 1e-8f);

    const float lam = 0.15f * (1.0f - g);
    const float tbg = tanhf(beta[0]) * g;

    float wm[9];
#pragma unroll
    for (int n = 0; n < 9; ++n) wm[n] = lam * e[n] * inv_se + tbg * hp[n] * hinv;

    const int ym = (y == 0) ? 1 : y - 1,   yp = (y == HL - 1) ? HL - 2 : y + 1;
    const int xm = (xx == 0) ? 1 : xx - 1, xp = (xx == WL - 1) ? WL - 2 : xx + 1;
    const int ry[3] = {ym, y, yp};
    const int rx[3] = {xm, xx, xp};

#pragma unroll
    for (int cl = 0; cl < 7; ++cl) {
        const int ci = grp * 7 + cl;
        const float* xb = x + (b * CIN + ci) * HW;
        float a = 0.f;
#pragma unroll
        for (int i = 0; i < 3; ++i)
#pragma unroll
            for (int j = 0; j < 3; ++j)
                a += xb[ry[i] * WL + rx[j]] * wm[i * 3 + j];
        g_ycomb[(b * CIN + ci) * HW + pix] = a;
    }
    if (grp == 0) g_lamb[b * HW + pix] = lam;
}

// ==========================================================================
// Kernel 4: high-res outputs. Thread = one 4x4 cell.
// ==========================================================================
__global__ __launch_bounds__(256) void final_kernel(
    const float* __restrict__ x, float* __restrict__ out)
{
    const int qx  = threadIdx.x;
    const int cyr = blockIdx.x * 3 + threadIdx.y;
    const int c   = blockIdx.y;
    const int b   = blockIdx.z;
    const int lpix = cyr * WL + qx;

    if (c == 21) {
        const float gv = g_raw[(b * 9 + 8) * HW + lpix];
        const float4 o = make_float4(gv, gv, gv, gv);
        float* dst = &out[OUT_G_OFF + b * HWO + (cyr * 4) * WOUTX + qx * 4];
#pragma unroll
        for (int jy = 0; jy < 4; ++jy) *(float4*)(dst + jy * WOUTX) = o;
        return;
    }

    const float sc = 80.0f / 323.0f;
    const float lam = g_lamb[b * HW + lpix];
    const float yc  = g_ycomb[(b * CIN + c) * HW + lpix];
    const float oml = 1.0f - lam;

    const float* xb = x + (b * CIN + c) * HW;
    int ia = (int)((float)(qx * 4) * sc);
    if (ia > WL - 3) ia = WL - 3;

    float* dst = &out[(b * CIN + c) * HWO + (cyr * 4) * WOUTX + qx * 4];

#pragma unroll
    for (int jy = 0; jy < 4; ++jy) {
        const int Y = cyr * 4 + jy;
        const float fy = (float)Y * sc;
        int iy = (int)fy; if (iy > HL - 2) iy = HL - 2;
        const float wy = fy - (float)iy;
        const float* r0p = xb + iy * WL + ia;
        const float a0 = r0p[0], a1 = r0p[1], a2 = r0p[2];
        const float b0 = r0p[WL], b1 = r0p[WL + 1], b2 = r0p[WL + 2];

        float res[4];
#pragma unroll
        for (int jx = 0; jx < 4; ++jx) {
            const int X = qx * 4 + jx;
            const float fx = (float)X * sc;
            int ix = (int)fx; if (ix > WL - 2) ix = WL - 2;
            const float wx = fx - (float)ix;
            const bool hi = (ix != ia);
            const float xL0 = hi ? a1 : a0, xR0 = hi ? a2 : a1;
            const float xL1 = hi ? b1 : b0, xR1 = hi ? b2 : b1;
            const float top = xL0 + (xR0 - xL0) * wx;
            const float bot = xL1 + (xR1 - xL1) * wx;
            const float xu  = top + (bot - top) * wy;
            res[jx] = xu * oml + yc;
        }
        *(float4*)(dst + jy * WOUTX) = make_float4(res[0], res[1], res[2], res[3]);
    }
}

// ==========================================================================
extern "C" void kernel_launch(void* const* d_in, const int* in_sizes, int n_in,
                              void* d_out, int out_size)
{
    const float* x    = (const float*)d_in[0];
    const float* w1o  = (const float*)d_in[1];
    const float* b1o  = (const float*)d_in[2];
    const float* w2o  = (const float*)d_in[3];
    const float* b2o  = (const float*)d_in[4];
    const float* w1g  = (const float*)d_in[5];
    const float* b1g  = (const float*)d_in[6];
    const float* w2g  = (const float*)d_in[7];
    const float* b2g  = (const float*)d_in[8];
    const float* beta = (const float*)d_in[9];
    float* out = (float*)d_out;

    pad_kernel<<<(PAD_N1 + PAD_N2 + 255) / 256, 256>>>(x);
    conv1_kernel<<<dim3(3, 24, Bn), 192>>>(w1o, b1o, w1g, b1g);
    conv2_kernel<<<dim3(9, 9, Bn), 64>>>(w2o, b2o, w2g, b2g, out);
    fuse_kernel<<<dim3(26, 3, Bn), 256>>>(x, beta);
    final_kernel<<<dim3(27, 22, Bn), dim3(81, 3, 1)>>>(x, out);
}

// round 5
// speedup vs baseline: 1.9282x; 1.0131x over previous
#include <cuda_runtime.h>
#include <math.h>

typedef unsigned long long ull;

// ---------------- problem constants ----------------
#define Bn    4
#define CIN   21
#define HL    81
#define WL    81
#define HW    6561
#define HWO   104976
#define WOUTX 324
#define XPW   88
#define XPP   7304        // 83*88

#define OUT_V_OFF 8817984
#define OUT_G_OFF 9027936

// ---------------- scratch ----------------
__device__ float g_xpad[Bn * CIN * XPP];
__device__ float g_hidden[Bn * 96 * XPP];
__device__ float g_raw[Bn * 9 * HW];

// ---------------- packed fp32x2 helpers ----------------
__device__ __forceinline__ ull pkf2(float lo, float hi) {
    ull r; asm("mov.b64 %0, {%1,%2};" : "=l"(r) : "f"(lo), "f"(hi)); return r;
}
__device__ __forceinline__ void upkf2(ull v, float& lo, float& hi) {
    asm("mov.b64 {%0,%1}, %2;" : "=f"(lo), "=f"(hi) : "l"(v));
}
__device__ __forceinline__ void ffma2(ull& d, ull a, ull b) {
    asm("fma.rn.f32x2 %0, %1, %2, %0;" : "+l"(d) : "l"(a), "l"(b));
}
__device__ __forceinline__ ull hilo(ull a, ull b) {
    float al, ah, bl, bh; upkf2(a, al, ah); upkf2(b, bl, bh); return pkf2(ah, bl);
}

// fast tanh / sigmoid via MUFU EX2
__device__ __forceinline__ float fast_tanh(float x) {
    const float e2 = __expf(2.0f * x);
    return 1.0f - __fdividef(2.0f, e2 + 1.0f);
}
__device__ __forceinline__ float fast_sigmoid(float x) {
    return __fdividef(1.0f, 1.0f + __expf(-x));
}

// ==========================================================================
// Kernel 0: build xpad (zero halo) + zero hidden halos.
// ==========================================================================
#define PAD_N1 (Bn * CIN * XPP)
#define PAD_N2 (Bn * 96 * 744)
__global__ void pad_kernel(const float* __restrict__ x)
{
    const int idx = blockIdx.x * 256 + threadIdx.x;
    if (idx < PAD_N1) {
        const int plane = idx / XPP;
        const int rem   = idx - plane * XPP;
        const int r     = rem / XPW;
        const int col   = rem - r * XPW;
        float v = 0.f;
        if (r >= 1 && r <= HL && col >= 1 && col <= WL)
            v = x[plane * HW + (r - 1) * WL + (col - 1)];
        g_xpad[idx] = v;
    } else if (idx < PAD_N1 + PAD_N2) {
        const int j2    = idx - PAD_N1;
        const int plane = j2 / 744;
        const int j     = j2 - plane * 744;
        int off;
        if (j < 88)       off = j;
        else if (j < 176) off = 82 * XPW + (j - 88);
        else {
            const int jj = j - 176;
            const int rr = 1 + jj / 7;
            const int cc = jj - (jj / 7) * 7;
            off = rr * XPW + ((cc == 0) ? 0 : 81 + cc);
        }
        g_hidden[plane * XPP + off] = 0.f;
    }
}

// ==========================================================================
// Kernel 1: conv1 (21 -> 96), ReLU. 3 rows x 4 px x 4 co per thread.
// ==========================================================================
__global__ __launch_bounds__(192) void conv1_kernel(
    const float* __restrict__ w1o, const float* __restrict__ b1o,
    const float* __restrict__ w1g, const float* __restrict__ b1g)
{
    __shared__ __align__(16) float sx[3 * 29 * XPW];
    __shared__ ull sw2[4 * 189];

    const int tile = blockIdx.x;
    const int cg   = blockIdx.y;
    const int b    = blockIdx.z;
    const int r0   = tile * 27;
    const int tid  = threadIdx.x;

    for (int i = tid; i < 4 * 189; i += 192) {
        const int co = i / 189, j = i - co * 189;
        const int co_out = cg * 4 + co;
        const float w = (co_out < 48) ? w1o[co_out * 189 + j] : w1g[(co_out - 48) * 189 + j];
        sw2[i] = pkf2(w, w);
    }

    const bool active = tid < 189;
    const int trp = active ? (tid / 21) : 0;
    const int tc  = active ? ((tid - trp * 21) * 4) : 0;
    const int trp3 = trp * 3;
    const int nvalid = (tc == 80) ? 1 : 4;

    ull acc[4][3][2];
#pragma unroll
    for (int co = 0; co < 4; ++co)
#pragma unroll
        for (int r = 0; r < 3; ++r) { acc[co][r][0] = 0ULL; acc[co][r][1] = 0ULL; }

    for (int cc = 0; cc < 7; ++cc) {
        __syncthreads();
        for (int i = tid; i < 3 * 29 * 22; i += 192) {
            const int c  = i / 638;
            const int rm = i - c * 638;
            const int lr = rm / 22;
            const int f4 = rm - lr * 22;
            ((float4*)sx)[(c * 29 + lr) * 22 + f4] =
                ((const float4*)g_xpad)[((b * CIN + cc * 3 + c) * XPP + (r0 + lr) * XPW) / 4 + f4];
        }
        __syncthreads();

        if (active) {
#pragma unroll
            for (int c = 0; c < 3; ++c) {
                ull PA[5], PAB[5], PB[5], PBC[5], PC[5];
#pragma unroll
                for (int rr = 0; rr < 5; ++rr) {
                    const float* rp = &sx[(c * 29 + trp3 + rr) * XPW + tc];
                    const ull A  = *(const ull*)rp;
                    const ull Bv = *(const ull*)(rp + 2);
                    const ull Cv = *(const ull*)(rp + 4);
                    PA[rr] = A; PB[rr] = Bv; PC[rr] = Cv;
                    PAB[rr] = hilo(A, Bv); PBC[rr] = hilo(Bv, Cv);
                }
                const int wb = (cc * 3 + c) * 9;
#pragma unroll
                for (int ky = 0; ky < 3; ++ky)
#pragma unroll
                    for (int kx = 0; kx < 3; ++kx)
#pragma unroll
                        for (int co = 0; co < 4; ++co) {
                            const ull w = sw2[co * 189 + wb + ky * 3 + kx];
#pragma unroll
                            for (int r = 0; r < 3; ++r) {
                                const int rw = r + ky;
                                ffma2(acc[co][r][0],
                                      kx == 0 ? PA[rw] : (kx == 1 ? PAB[rw] : PB[rw]), w);
                                ffma2(acc[co][r][1],
                                      kx == 0 ? PB[rw] : (kx == 1 ? PBC[rw] : PC[rw]), w);
                            }
                        }
            }
        }
    }

    if (active) {
#pragma unroll
        for (int co = 0; co < 4; ++co) {
            const int co_out = cg * 4 + co;
            const float bias = (co_out < 48) ? b1o[co_out] : b1g[co_out - 48];
#pragma unroll
            for (int r = 0; r < 3; ++r) {
                const int orow = r0 + trp3 + r;
                float* dst = &g_hidden[(b * 96 + co_out) * XPP + (orow + 1) * XPW + tc + 1];
                float v[4];
                upkf2(acc[co][r][0], v[0], v[1]);
                upkf2(acc[co][r][1], v[2], v[3]);
#pragma unroll
                for (int p = 0; p < 4; ++p)
                    if (p < nvalid) dst[p] = fmaxf(v[p] + bias, 0.f);
            }
        }
    }
}

// ==========================================================================
// Kernel 2: conv2 heads. 3 rows x 4 px x 1 co per thread.
// ==========================================================================
__global__ __launch_bounds__(64) void conv2_kernel(
    const float* __restrict__ w2o, const float* __restrict__ b2o,
    const float* __restrict__ w2g, const float* __restrict__ b2g,
    float* __restrict__ out)
{
    __shared__ __align__(16) float sx[3 * 11 * XPW];
    __shared__ ull sw2[432];

    const int tile = blockIdx.x;
    const int co   = blockIdx.y;
    const int b    = blockIdx.z;
    const int r0   = tile * 9;
    const int tid  = threadIdx.x;

    const int chbase = (co < 8) ? 0 : 48;
    const float* wsrc = (co < 8) ? (w2o + co * 432) : w2g;
    for (int i = tid; i < 432; i += 64) sw2[i] = pkf2(wsrc[i], wsrc[i]);

    const bool active = tid < 63;
    const int trp = active ? (tid / 21) : 0;
    const int tc  = active ? ((tid - trp * 21) * 4) : 0;
    const int trp3 = trp * 3;
    const int nvalid = (tc == 80) ? 1 : 4;

    ull acc[3][2];
#pragma unroll
    for (int r = 0; r < 3; ++r) { acc[r][0] = 0ULL; acc[r][1] = 0ULL; }

    for (int cc = 0; cc < 16; ++cc) {
        __syncthreads();
        for (int i = tid; i < 3 * 11 * 22; i += 64) {
            const int c  = i / 242;
            const int rm = i - c * 242;
            const int lr = rm / 22;
            const int f4 = rm - lr * 22;
            ((float4*)sx)[(c * 11 + lr) * 22 + f4] =
                ((const float4*)g_hidden)[((b * 96 + chbase + cc * 3 + c) * XPP + (r0 + lr) * XPW) / 4 + f4];
        }
        __syncthreads();

        if (active) {
#pragma unroll
            for (int c = 0; c < 3; ++c) {
                ull PA[5], PAB[5], PB[5], PBC[5], PC[5];
#pragma unroll
                for (int rr = 0; rr < 5; ++rr) {
                    const float* rp = &sx[(c * 11 + trp3 + rr) * XPW + tc];
                    const ull A  = *(const ull*)rp;
                    const ull Bv = *(const ull*)(rp + 2);
                    const ull Cv = *(const ull*)(rp + 4);
                    PA[rr] = A; PB[rr] = Bv; PC[rr] = Cv;
                    PAB[rr] = hilo(A, Bv); PBC[rr] = hilo(Bv, Cv);
                }
                const int wb = (cc * 3 + c) * 9;
#pragma unroll
                for (int ky = 0; ky < 3; ++ky)
#pragma unroll
                    for (int kx = 0; kx < 3; ++kx) {
                        const ull w = sw2[wb + ky * 3 + kx];
#pragma unroll
                        for (int r = 0; r < 3; ++r) {
                            const int rw = r + ky;
                            ffma2(acc[r][0],
                                  kx == 0 ? PA[rw] : (kx == 1 ? PAB[rw] : PB[rw]), w);
                            ffma2(acc[r][1],
                                  kx == 0 ? PB[rw] : (kx == 1 ? PBC[rw] : PC[rw]), w);
                        }
                    }
            }
        }
    }

    if (active) {
        const float bias = (co < 8) ? b2o[co] : b2g[0];
#pragma unroll
        for (int r = 0; r < 3; ++r) {
            const int orow = r0 + trp3 + r;
            float v[4];
            upkf2(acc[r][0], v[0], v[1]);
            upkf2(acc[r][1], v[2], v[3]);
#pragma unroll
            for (int p = 0; p < 4; ++p) {
                if (p >= nvalid) continue;
                const int pix = orow * WL + tc + p;
                const float raw = v[p] + bias;
                if (co < 8) {
                    const float t = fast_tanh(raw);
                    g_raw[(b * 9 + co) * HW + pix] = t;
                    out[OUT_V_OFF + (b * 8 + co) * HW + pix] = t;
                } else {
                    g_raw[(b * 9 + 8) * HW + pix] = fast_sigmoid(raw);
                }
            }
        }
    }
}

// ==========================================================================
// Kernel 3 (merged fuse + upsample): per lowres pixel x 7-channel group.
// Computes wm, then per channel: 3x3 reflect taps -> ycomb AND the 16
// high-res outputs directly (bilinear taps are a subset of the 3x3 patch:
// iy in {y-1,y}, ix in {x-1,x}).
// grid (26, 3, 4); block 256.
// ==========================================================================
__global__ __launch_bounds__(256) void upfuse_kernel(
    const float* __restrict__ x, const float* __restrict__ beta,
    float* __restrict__ out)
{
    const int pix = blockIdx.x * blockDim.x + threadIdx.x;
    if (pix >= HW) return;
    const int grp = blockIdx.y;
    const int b   = blockIdx.z;
    const int y = pix / WL, xx = pix - y * WL;

    // ---- mask construction ----
    const float* vr = g_raw + b * 9 * HW;
    const float p0 = vr[0 * HW + pix] - vr[4 * HW + pix];
    const float p1 = vr[1 * HW + pix] - vr[5 * HW + pix];
    const float p2 = vr[2 * HW + pix] - vr[6 * HW + pix];
    const float p3 = vr[3 * HW + pix] - vr[7 * HW + pix];
    const float g  = vr[8 * HW + pix];

    const float k00 = (p0 + p1 + p2) * 0.125f;
    const float k01 = (p1 + p2 + p3) * 0.125f;
    const float k02 = (-p0 + p2 + p3) * 0.125f;
    const float k10 = (p0 + p1 - p3) * 0.125f;

    float kb[9];
    kb[0] = k00;  kb[1] = k01;  kb[2] = k02;
    kb[3] = k10;  kb[4] = 2.5f; kb[5] = -k10;
    kb[6] = -k02; kb[7] = -k01; kb[8] = -k00;

    float mx = kb[0];
#pragma unroll
    for (int n = 1; n < 9; ++n) mx = fmaxf(mx, kb[n]);
    float e[9], se = 0.f;
#pragma unroll
    for (int n = 0; n < 9; ++n) { e[n] = __expf((kb[n] - mx) * 2.0f); se += e[n]; }
    const float inv_se = __fdividef(1.0f, se);

    const float mean = 2.5f / 9.0f;
    float sa = 0.f;
#pragma unroll
    for (int n = 0; n < 9; ++n) sa += fabsf(kb[n] - mean);
    const float hinv = __fdividef(1.0f, sa + 1e-8f);

    const float lam = 0.15f * (1.0f - g);
    const float tbg = tanhf(beta[0]) * g;
    const float oml = 1.0f - lam;

    float wm[9];
#pragma unroll
    for (int n = 0; n < 9; ++n) wm[n] = lam * e[n] * inv_se + tbg * (kb[n] - mean) * hinv;

    // ---- g_up (group 0 only) ----
    if (grp == 0) {
        const float4 gq = make_float4(g, g, g, g);
        float* gd = &out[OUT_G_OFF + b * HWO + (y * 4) * WOUTX + xx * 4];
#pragma unroll
        for (int jy = 0; jy < 4; ++jy) *(float4*)(gd + jy * WOUTX) = gq;
    }

    // ---- bilinear geometry (shared across channels) ----
    const float sc = 80.0f / 323.0f;
    float wyv[4], wxv[4];
    bool rlo[4], clo[4];      // true -> use taps (0,1), else (1,2)
#pragma unroll
    for (int j = 0; j < 4; ++j) {
        const float fy = (float)(y * 4 + j) * sc;
        int iy = (int)fy; if (iy > HL - 2) iy = HL - 2;
        wyv[j] = fy - (float)iy;
        rlo[j] = (iy != y);
        const float fx = (float)(xx * 4 + j) * sc;
        int ix = (int)fx; if (ix > WL - 2) ix = WL - 2;
        wxv[j] = fx - (float)ix;
        clo[j] = (ix != xx);
    }

    // reflect tap indices
    const int ym = (y == 0) ? 1 : y - 1,   yp = (y == HL - 1) ? HL - 2 : y + 1;
    const int xm = (xx == 0) ? 1 : xx - 1, xp = (xx == WL - 1) ? WL - 2 : xx + 1;
    const int ry[3] = {ym, y, yp};
    const int rx[3] = {xm, xx, xp};

    for (int cl = 0; cl < 7; ++cl) {
        const int ci = grp * 7 + cl;
        const float* xb = x + (b * CIN + ci) * HW;

        float t[3][3];
#pragma unroll
        for (int i = 0; i < 3; ++i)
#pragma unroll
            for (int j = 0; j < 3; ++j)
                t[i][j] = xb[ry[i] * WL + rx[j]];

        float yc = 0.f;
#pragma unroll
        for (int i = 0; i < 3; ++i)
#pragma unroll
            for (int j = 0; j < 3; ++j)
                yc += t[i][j] * wm[i * 3 + j];

        float* dst = &out[(b * CIN + ci) * HWO + (y * 4) * WOUTX + xx * 4];
#pragma unroll
        for (int jy = 0; jy < 4; ++jy) {
            const float wy = wyv[jy];
            // select the two true source rows from taps
            const float rA0 = rlo[jy] ? t[0][0] : t[1][0];
            const float rA1 = rlo[jy] ? t[0][1] : t[1][1];
            const float rA2 = rlo[jy] ? t[0][2] : t[1][2];
            const float rB0 = rlo[jy] ? t[1][0] : t[2][0];
            const float rB1 = rlo[jy] ? t[1][1] : t[2][1];
            const float rB2 = rlo[jy] ? t[1][2] : t[2][2];

            float res[4];
#pragma unroll
            for (int jx = 0; jx < 4; ++jx) {
                const float wx = wxv[jx];
                const float aL = clo[jx] ? rA0 : rA1;
                const float aR = clo[jx] ? rA1 : rA2;
                const float bL = clo[jx] ? rB0 : rB1;
                const float bR = clo[jx] ? rB1 : rB2;
                const float top = aL + (aR - aL) * wx;
                const float bot = bL + (bR - bL) * wx;
                const float xu  = top + (bot - top) * wy;
                res[jx] = xu * oml + yc;
            }
            *(float4*)(dst + jy * WOUTX) = make_float4(res[0], res[1], res[2], res[3]);
        }
    }
}

// ==========================================================================
extern "C" void kernel_launch(void* const* d_in, const int* in_sizes, int n_in,
                              void* d_out, int out_size)
{
    const float* x    = (const float*)d_in[0];
    const float* w1o  = (const float*)d_in[1];
    const float* b1o  = (const float*)d_in[2];
    const float* w2o  = (const float*)d_in[3];
    const float* b2o  = (const float*)d_in[4];
    const float* w1g  = (const float*)d_in[5];
    const float* b1g  = (const float*)d_in[6];
    const float* w2g  = (const float*)d_in[7];
    const float* b2g  = (const float*)d_in[8];
    const float* beta = (const float*)d_in[9];
    float* out = (float*)d_out;

    pad_kernel<<<(PAD_N1 + PAD_N2 + 255) / 256, 256>>>(x);
    conv1_kernel<<<dim3(3, 24, Bn), 192>>>(w1o, b1o, w1g, b1g);
    conv2_kernel<<<dim3(9, 9, Bn), 64>>>(w2o, b2o, w2g, b2g, out);
    upfuse_kernel<<<dim3(26, 3, Bn), 256>>>(x, beta, out);
}

// round 6
// speedup vs baseline: 2.0944x; 1.0862x over previous
#include <cuda_runtime.h>
#include <math.h>

typedef unsigned long long ull;

// ---------------- problem constants ----------------
#define Bn    4
#define CIN   21
#define HL    81
#define WL    81
#define HW    6561
#define HWO   104976
#define WOUTX 324
#define XPW   88
#define XPP   7304        // 83*88

#define OUT_V_OFF 8817984
#define OUT_G_OFF 9027936

// ---------------- scratch ----------------
__device__ float g_xpad[Bn * CIN * XPP];
__device__ float g_hidden[Bn * 96 * XPP];
__device__ float g_raw[Bn * 9 * HW];

// ---------------- packed fp32x2 helpers ----------------
__device__ __forceinline__ ull pkf2(float lo, float hi) {
    ull r; asm("mov.b64 %0, {%1,%2};" : "=l"(r) : "f"(lo), "f"(hi)); return r;
}
__device__ __forceinline__ void upkf2(ull v, float& lo, float& hi) {
    asm("mov.b64 {%0,%1}, %2;" : "=f"(lo), "=f"(hi) : "l"(v));
}
__device__ __forceinline__ void ffma2(ull& d, ull a, ull b) {
    asm("fma.rn.f32x2 %0, %1, %2, %0;" : "+l"(d) : "l"(a), "l"(b));
}
__device__ __forceinline__ ull hilo(ull a, ull b) {
    float al, ah, bl, bh; upkf2(a, al, ah); upkf2(b, bl, bh); return pkf2(ah, bl);
}

__device__ __forceinline__ float fast_tanh(float x) {
    const float e2 = __expf(2.0f * x);
    return 1.0f - __fdividef(2.0f, e2 + 1.0f);
}
__device__ __forceinline__ float fast_sigmoid(float x) {
    return __fdividef(1.0f, 1.0f + __expf(-x));
}

// ==========================================================================
// Kernel 0: build xpad (zero halo) + zero hidden halos.
// ==========================================================================
#define PAD_N1 (Bn * CIN * XPP)
#define PAD_N2 (Bn * 96 * 744)
__global__ void pad_kernel(const float* __restrict__ x)
{
    const int idx = blockIdx.x * 256 + threadIdx.x;
    if (idx < PAD_N1) {
        const int plane = idx / XPP;
        const int rem   = idx - plane * XPP;
        const int r     = rem / XPW;
        const int col   = rem - r * XPW;
        float v = 0.f;
        if (r >= 1 && r <= HL && col >= 1 && col <= WL)
            v = x[plane * HW + (r - 1) * WL + (col - 1)];
        g_xpad[idx] = v;
    } else if (idx < PAD_N1 + PAD_N2) {
        const int j2    = idx - PAD_N1;
        const int plane = j2 / 744;
        const int j     = j2 - plane * 744;
        int off;
        if (j < 88)       off = j;
        else if (j < 176) off = 82 * XPW + (j - 88);
        else {
            const int jj = j - 176;
            const int rr = 1 + jj / 7;
            const int cc = jj - (jj / 7) * 7;
            off = rr * XPW + ((cc == 0) ? 0 : 81 + cc);
        }
        g_hidden[plane * XPP + off] = 0.f;
    }
}

// ==========================================================================
// Kernel 1: conv1 (21 -> 96), ReLU. 3 rows x 4 px x 4 co per thread.
// ==========================================================================
__global__ __launch_bounds__(192) void conv1_kernel(
    const float* __restrict__ w1o, const float* __restrict__ b1o,
    const float* __restrict__ w1g, const float* __restrict__ b1g)
{
    __shared__ __align__(16) float sx[3 * 29 * XPW];
    __shared__ ull sw2[4 * 189];

    const int tile = blockIdx.x;
    const int cg   = blockIdx.y;
    const int b    = blockIdx.z;
    const int r0   = tile * 27;
    const int tid  = threadIdx.x;

    for (int i = tid; i < 4 * 189; i += 192) {
        const int co = i / 189, j = i - co * 189;
        const int co_out = cg * 4 + co;
        const float w = (co_out < 48) ? w1o[co_out * 189 + j] : w1g[(co_out - 48) * 189 + j];
        sw2[i] = pkf2(w, w);
    }

    const bool active = tid < 189;
    const int trp = active ? (tid / 21) : 0;
    const int tc  = active ? ((tid - trp * 21) * 4) : 0;
    const int trp3 = trp * 3;
    const int nvalid = (tc == 80) ? 1 : 4;

    ull acc[4][3][2];
#pragma unroll
    for (int co = 0; co < 4; ++co)
#pragma unroll
        for (int r = 0; r < 3; ++r) { acc[co][r][0] = 0ULL; acc[co][r][1] = 0ULL; }

    for (int cc = 0; cc < 7; ++cc) {
        __syncthreads();
        for (int i = tid; i < 3 * 29 * 22; i += 192) {
            const int c  = i / 638;
            const int rm = i - c * 638;
            const int lr = rm / 22;
            const int f4 = rm - lr * 22;
            ((float4*)sx)[(c * 29 + lr) * 22 + f4] =
                ((const float4*)g_xpad)[((b * CIN + cc * 3 + c) * XPP + (r0 + lr) * XPW) / 4 + f4];
        }
        __syncthreads();

        if (active) {
#pragma unroll
            for (int c = 0; c < 3; ++c) {
                ull PA[5], PAB[5], PB[5], PBC[5], PC[5];
#pragma unroll
                for (int rr = 0; rr < 5; ++rr) {
                    const float* rp = &sx[(c * 29 + trp3 + rr) * XPW + tc];
                    const ull A  = *(const ull*)rp;
                    const ull Bv = *(const ull*)(rp + 2);
                    const ull Cv = *(const ull*)(rp + 4);
                    PA[rr] = A; PB[rr] = Bv; PC[rr] = Cv;
                    PAB[rr] = hilo(A, Bv); PBC[rr] = hilo(Bv, Cv);
                }
                const int wb = (cc * 3 + c) * 9;
#pragma unroll
                for (int ky = 0; ky < 3; ++ky)
#pragma unroll
                    for (int kx = 0; kx < 3; ++kx)
#pragma unroll
                        for (int co = 0; co < 4; ++co) {
                            const ull w = sw2[co * 189 + wb + ky * 3 + kx];
#pragma unroll
                            for (int r = 0; r < 3; ++r) {
                                const int rw = r + ky;
                                ffma2(acc[co][r][0],
                                      kx == 0 ? PA[rw] : (kx == 1 ? PAB[rw] : PB[rw]), w);
                                ffma2(acc[co][r][1],
                                      kx == 0 ? PB[rw] : (kx == 1 ? PBC[rw] : PC[rw]), w);
                            }
                        }
            }
        }
    }

    if (active) {
#pragma unroll
        for (int co = 0; co < 4; ++co) {
            const int co_out = cg * 4 + co;
            const float bias = (co_out < 48) ? b1o[co_out] : b1g[co_out - 48];
#pragma unroll
            for (int r = 0; r < 3; ++r) {
                const int orow = r0 + trp3 + r;
                float* dst = &g_hidden[(b * 96 + co_out) * XPP + (orow + 1) * XPW + tc + 1];
                float v[4];
                upkf2(acc[co][r][0], v[0], v[1]);
                upkf2(acc[co][r][1], v[2], v[3]);
#pragma unroll
                for (int p = 0; p < 4; ++p)
                    if (p < nvalid) dst[p] = fmaxf(v[p] + bias, 0.f);
            }
        }
    }
}

// ==========================================================================
// Kernel 2: conv2 heads, all 9 per block. Block 576 (567 active):
// thread = 1 row x 4 px x 1 co; tile = 3 rows. All 96 ch staged ONCE
// (chunks of 3 o-src + 3 g-src channels; o-heads and gate consume in
// parallel). grid (27, Bn).
// ==========================================================================
__global__ __launch_bounds__(576) void conv2_kernel(
    const float* __restrict__ w2o, const float* __restrict__ b2o,
    const float* __restrict__ w2g, const float* __restrict__ b2g,
    float* __restrict__ out)
{
    __shared__ __align__(16) float sx[6 * 5 * XPW];   // 10.6 KB
    __shared__ ull sw2[9 * 432];                       // 31.1 KB

    const int tile = blockIdx.x;
    const int b    = blockIdx.y;
    const int r0   = tile * 3;
    const int tid  = threadIdx.x;

    for (int i = tid; i < 9 * 432; i += 576) {
        const int co = i / 432, j = i - co * 432;
        const float w = (co < 8) ? w2o[co * 432 + j] : w2g[j];
        sw2[i] = pkf2(w, w);
    }

    const bool active = tid < 567;
    const int co  = active ? (tid / 63) : 0;
    const int s   = active ? (tid - co * 63) : 0;
    const int row = s / 21;
    const int tc  = (s - row * 21) * 4;
    const int nvalid = (tc == 80) ? 1 : 4;
    const int csel = (co == 8) ? 3 : 0;    // gate reads staged channels 3..5

    ull a0 = 0ULL, a1 = 0ULL;

    for (int cc = 0; cc < 16; ++cc) {
        __syncthreads();
        // stage 6 channels x 5 rows x 22 float4
        for (int i = tid; i < 660; i += 576) {
            const int c  = i / 110;
            const int rm = i - c * 110;
            const int lr = rm / 22;
            const int f4 = rm - lr * 22;
            const int ch = (c < 3) ? (cc * 3 + c) : (48 + cc * 3 + (c - 3));
            ((float4*)sx)[(c * 5 + lr) * 22 + f4] =
                ((const float4*)g_hidden)[((b * 96 + ch) * XPP + (r0 + lr) * XPW) / 4 + f4];
        }
        __syncthreads();

        if (active) {
#pragma unroll
            for (int c = 0; c < 3; ++c) {
                ull PA[3], PAB[3], PB[3], PBC[3], PC[3];
#pragma unroll
                for (int rr = 0; rr < 3; ++rr) {
                    const float* rp = &sx[((csel + c) * 5 + row + rr) * XPW + tc];
                    const ull A  = *(const ull*)rp;
                    const ull Bv = *(const ull*)(rp + 2);
                    const ull Cv = *(const ull*)(rp + 4);
                    PA[rr] = A; PB[rr] = Bv; PC[rr] = Cv;
                    PAB[rr] = hilo(A, Bv); PBC[rr] = hilo(Bv, Cv);
                }
                const int wb = co * 432 + (cc * 3 + c) * 9;
#pragma unroll
                for (int ky = 0; ky < 3; ++ky)
#pragma unroll
                    for (int kx = 0; kx < 3; ++kx) {
                        const ull w = sw2[wb + ky * 3 + kx];
                        ffma2(a0, kx == 0 ? PA[ky] : (kx == 1 ? PAB[ky] : PB[ky]), w);
                        ffma2(a1, kx == 0 ? PB[ky] : (kx == 1 ? PBC[ky] : PC[ky]), w);
                    }
            }
        }
    }

    if (active) {
        const float bias = (co < 8) ? b2o[co] : b2g[0];
        const int orow = r0 + row;
        float v[4];
        upkf2(a0, v[0], v[1]);
        upkf2(a1, v[2], v[3]);
#pragma unroll
        for (int p = 0; p < 4; ++p) {
            if (p >= nvalid) continue;
            const int pix = orow * WL + tc + p;
            const float raw = v[p] + bias;
            if (co < 8) {
                const float t = fast_tanh(raw);
                g_raw[(b * 9 + co) * HW + pix] = t;
                out[OUT_V_OFF + (b * 8 + co) * HW + pix] = t;
            } else {
                g_raw[(b * 9 + 8) * HW + pix] = fast_sigmoid(raw);
            }
        }
    }
}

// ==========================================================================
// Kernel 3 (fuse + upsample): per lowres pixel x 7-channel group.
// Bilinear done via per-pixel precomputed 3-tap row/col weight vectors
// (zero at the unused tap) -> pure FFMA2, no selects in the channel loop.
// grid (26, 3, 4); block 256.
// ==========================================================================
__global__ __launch_bounds__(256) void upfuse_kernel(
    const float* __restrict__ x, const float* __restrict__ beta,
    float* __restrict__ out)
{
    const int pix = blockIdx.x * blockDim.x + threadIdx.x;
    if (pix >= HW) return;
    const int grp = blockIdx.y;
    const int b   = blockIdx.z;
    const int y = pix / WL, xx = pix - y * WL;

    // ---- mask construction ----
    const float* vr = g_raw + b * 9 * HW;
    const float p0 = vr[0 * HW + pix] - vr[4 * HW + pix];
    const float p1 = vr[1 * HW + pix] - vr[5 * HW + pix];
    const float p2 = vr[2 * HW + pix] - vr[6 * HW + pix];
    const float p3 = vr[3 * HW + pix] - vr[7 * HW + pix];
    const float g  = vr[8 * HW + pix];

    const float k00 = (p0 + p1 + p2) * 0.125f;
    const float k01 = (p1 + p2 + p3) * 0.125f;
    const float k02 = (-p0 + p2 + p3) * 0.125f;
    const float k10 = (p0 + p1 - p3) * 0.125f;

    float kb[9];
    kb[0] = k00;  kb[1] = k01;  kb[2] = k02;
    kb[3] = k10;  kb[4] = 2.5f; kb[5] = -k10;
    kb[6] = -k02; kb[7] = -k01; kb[8] = -k00;

    float mx = kb[0];
#pragma unroll
    for (int n = 1; n < 9; ++n) mx = fmaxf(mx, kb[n]);
    float e[9], se = 0.f;
#pragma unroll
    for (int n = 0; n < 9; ++n) { e[n] = __expf((kb[n] - mx) * 2.0f); se += e[n]; }
    const float inv_se = __fdividef(1.0f, se);

    const float mean = 2.5f / 9.0f;
    float sa = 0.f;
#pragma unroll
    for (int n = 0; n < 9; ++n) sa += fabsf(kb[n] - mean);
    const float hinv = __fdividef(1.0f, sa + 1e-8f);

    const float lam = 0.15f * (1.0f - g);
    const float tbg = tanhf(beta[0]) * g;
    const float oml = 1.0f - lam;

    float wm[9];
#pragma unroll
    for (int n = 0; n < 9; ++n) wm[n] = lam * e[n] * inv_se + tbg * (kb[n] - mean) * hinv;

    // ---- g_up (group 0 only) ----
    if (grp == 0) {
        const float4 gq = make_float4(g, g, g, g);
        float* gd = &out[OUT_G_OFF + b * HWO + (y * 4) * WOUTX + xx * 4];
#pragma unroll
        for (int jy = 0; jy < 4; ++jy) *(float4*)(gd + jy * WOUTX) = gq;
    }

    // ---- per-pixel bilinear weight vectors (3 taps, zero at unused) ----
    const float sc = 80.0f / 323.0f;
    float wx3[4][3];
#pragma unroll
    for (int j = 0; j < 4; ++j) {
        const float fx = (float)(xx * 4 + j) * sc;
        int ix = (int)fx; if (ix > WL - 2) ix = WL - 2;
        const float wx = fx - (float)ix;
        const bool lo = (ix != xx);            // taps (0,1) else (1,2)
        wx3[j][0] = lo ? (1.f - wx) : 0.f;
        wx3[j][1] = lo ? wx : (1.f - wx);
        wx3[j][2] = lo ? 0.f : wx;
    }
    ull wxp[2][3];
#pragma unroll
    for (int p = 0; p < 2; ++p)
#pragma unroll
        for (int j = 0; j < 3; ++j)
            wxp[p][j] = pkf2(wx3[2 * p][j], wx3[2 * p + 1][j]);

    ull wyp[4][3];
#pragma unroll
    for (int j = 0; j < 4; ++j) {
        const float fy = (float)(y * 4 + j) * sc;
        int iy = (int)fy; if (iy > HL - 2) iy = HL - 2;
        const float wy = fy - (float)iy;
        const bool lo = (iy != y);
        const float w0 = oml * (lo ? (1.f - wy) : 0.f);
        const float w1 = oml * (lo ? wy : (1.f - wy));
        const float w2 = oml * (lo ? 0.f : wy);
        wyp[j][0] = pkf2(w0, w0);
        wyp[j][1] = pkf2(w1, w1);
        wyp[j][2] = pkf2(w2, w2);
    }

    // reflect tap indices
    const int ym = (y == 0) ? 1 : y - 1,   yp = (y == HL - 1) ? HL - 2 : y + 1;
    const int xm = (xx == 0) ? 1 : xx - 1, xp = (xx == WL - 1) ? WL - 2 : xx + 1;
    const int ry[3] = {ym, y, yp};
    const int rx[3] = {xm, xx, xp};

    for (int cl = 0; cl < 7; ++cl) {
        const int ci = grp * 7 + cl;
        const float* xb = x + (b * CIN + ci) * HW;

        float t[3][3];
#pragma unroll
        for (int i = 0; i < 3; ++i)
#pragma unroll
            for (int j = 0; j < 3; ++j)
                t[i][j] = xb[ry[i] * WL + rx[j]];

        float yc = 0.f;
#pragma unroll
        for (int i = 0; i < 3; ++i)
#pragma unroll
            for (int j = 0; j < 3; ++j)
                yc += t[i][j] * wm[i * 3 + j];
        const ull yc2 = pkf2(yc, yc);

        // column interpolation: cvp[i][p] = sum_j t[i][j] * wx(jx pair p)
        ull cvp[3][2];
#pragma unroll
        for (int i = 0; i < 3; ++i) { cvp[i][0] = 0ULL; cvp[i][1] = 0ULL; }
#pragma unroll
        for (int i = 0; i < 3; ++i)
#pragma unroll
            for (int j = 0; j < 3; ++j) {
                const ull td = pkf2(t[i][j], t[i][j]);
                ffma2(cvp[i][0], td, wxp[0][j]);
                ffma2(cvp[i][1], td, wxp[1][j]);
            }

        float* dst = &out[(b * CIN + ci) * HWO + (y * 4) * WOUTX + xx * 4];
#pragma unroll
        for (int jy = 0; jy < 4; ++jy) {
            ull r0 = yc2, r1 = yc2;
#pragma unroll
            for (int i = 0; i < 3; ++i) {
                ffma2(r0, cvp[i][0], wyp[jy][i]);
                ffma2(r1, cvp[i][1], wyp[jy][i]);
            }
            float o0, o1, o2, o3;
            upkf2(r0, o0, o1);
            upkf2(r1, o2, o3);
            *(float4*)(dst + jy * WOUTX) = make_float4(o0, o1, o2, o3);
        }
    }
}

// ==========================================================================
extern "C" void kernel_launch(void* const* d_in, const int* in_sizes, int n_in,
                              void* d_out, int out_size)
{
    const float* x    = (const float*)d_in[0];
    const float* w1o  = (const float*)d_in[1];
    const float* b1o  = (const float*)d_in[2];
    const float* w2o  = (const float*)d_in[3];
    const float* b2o  = (const float*)d_in[4];
    const float* w1g  = (const float*)d_in[5];
    const float* b1g  = (const float*)d_in[6];
    const float* w2g  = (const float*)d_in[7];
    const float* b2g  = (const float*)d_in[8];
    const float* beta = (const float*)d_in[9];
    float* out = (float*)d_out;

    pad_kernel<<<(PAD_N1 + PAD_N2 + 255) / 256, 256>>>(x);
    conv1_kernel<<<dim3(3, 24, Bn), 192>>>(w1o, b1o, w1g, b1g);
    conv2_kernel<<<dim3(27, Bn), 576>>>(w2o, b2o, w2g, b2g, out);
    upfuse_kernel<<<dim3(26, 3, Bn), 256>>>(x, beta, out);
}